// round 17
// baseline (speedup 1.0000x reference)
#include <cuda_runtime.h>

// ShadingLayer: out[b,c,h,w] = sum_k L[b,c,k] * H_k(n[b,:,h,w])
// R16 = R2 champion (8192x256, 2 float4-groups/thread, 6 front-batched
//       128-bit loads, .cs streaming stores, reg-folded coefficients)
//       with loads on the NON-COHERENT read-only path + evict-first:
//       ld.global.nc.cs.v4.f32 (LDG.E.NC, cs) instead of generic ld.global.cs.
//       Input is const __restrict__ (never aliased by the output), so .nc
//       is safe; nc uses the read-only L1tex allocation/ordering class.
//
// Series conclusion (16 rounds): kernel is at the DRAM ceiling for a 1:1
// interleaved fp32 R/W stream (~6.0-6.2 TB/s, 75-78% of 8 TB/s spec).
//
// d_in[0]: recnormalch fp32 (64,3,512,512)
// d_in[1]: fc_light    fp32 (64,27)
// d_out  : fp32 (64,3,512,512)

#define C1f 0.8862269254527580f   // pi       * sqrt(1/(4pi))
#define C2f 1.0233267079464885f   // (2pi/3)  * sqrt(3/(4pi))
#define C3f 0.2477079561003757f   // (pi/4)*0.5*sqrt(5/(4pi))
#define C4f 0.8580855308097834f   // (pi/4)*3 * sqrt(5/(12pi))
#define C5f 0.4290427654048917f   // (pi/4)*3 * sqrt(5/(48pi))

static __device__ __forceinline__ float4 ldnccs4(const float* p) {
    float4 v;
    asm("ld.global.nc.cs.v4.f32 {%0,%1,%2,%3}, [%4];"
        : "=f"(v.x), "=f"(v.y), "=f"(v.z), "=f"(v.w)
        : "l"(p));
    return v;
}
static __device__ __forceinline__ void stcs4(float* p, float4 v) {
    __stcs(reinterpret_cast<float4*>(p), v);
}

__global__ __launch_bounds__(256)
void shading_kernel(const float* __restrict__ nrm,
                    const float* __restrict__ light,
                    float* __restrict__ out) {
    constexpr int HW = 512 * 512;        // pixels per plane
    // 65536 float4-groups/plane; 512 groups per block -> 128 blocks/batch
    const unsigned bid = blockIdx.x;
    const int b   = bid >> 7;            // batch
    const int blk = bid & 127;           // block within batch
    const int v0  = blk * 512 + threadIdx.x;   // first float4-group
    // second group = v0 + 256 (still coalesced across the block)

    const float* nb = nrm + (size_t)b * 3 * HW;

    // ---- front-batch all 6 data loads (MLP=6, read-only nc path) ----
    const float* p0 = nb + (size_t)v0 * 4;
    const float* p1 = p0 + 1024;               // +256 groups * 4 floats
    float4 X0 = ldnccs4(p0);
    float4 Y0 = ldnccs4(p0 + HW);
    float4 Z0 = ldnccs4(p0 + 2 * HW);
    float4 X1 = ldnccs4(p1);
    float4 Y1 = ldnccs4(p1 + HW);
    float4 Z1 = ldnccs4(p1 + 2 * HW);

    // ---- fold light coefficients (L2-broadcast hits) ----
    const float* Lb = light + b * 27;
    float a[3][9];
    #pragma unroll
    for (int c = 0; c < 3; c++) {
        a[c][0] = C1f * __ldg(Lb + 9 * c + 0);
        a[c][1] = C2f * __ldg(Lb + 9 * c + 1);
        a[c][2] = C2f * __ldg(Lb + 9 * c + 2);
        a[c][3] = C2f * __ldg(Lb + 9 * c + 3);
        a[c][4] = C3f * __ldg(Lb + 9 * c + 4);
        a[c][5] = C4f * __ldg(Lb + 9 * c + 5);
        a[c][6] = C4f * __ldg(Lb + 9 * c + 6);
        a[c][7] = C5f * __ldg(Lb + 9 * c + 7);
        a[c][8] = C4f * __ldg(Lb + 9 * c + 8);
    }

    float* ob = out + (size_t)b * 3 * HW;

    #pragma unroll
    for (int g = 0; g < 2; g++) {
        const float4 X = g ? X1 : X0;
        const float4 Y = g ? Y1 : Y0;
        const float4 Z = g ? Z1 : Z0;
        const float xs[4] = {X.x, X.y, X.z, X.w};
        const float ys[4] = {Y.x, Y.y, Y.z, Y.w};
        const float zs[4] = {Z.x, Z.y, Z.z, Z.w};
        float o[3][4];

        #pragma unroll
        for (int j = 0; j < 4; j++) {
            const float x = xs[j], y = ys[j], z = zs[j];
            const float xx = x * x;
            const float yy = y * y;
            const float b5 = 2.0f * z * z - xx - yy;
            const float b6 = x * z;
            const float b7 = y * z;
            const float b8 = xx - yy;
            const float b9 = x * y;
            #pragma unroll
            for (int c = 0; c < 3; c++) {
                float r = a[c][0];
                r = fmaf(a[c][1], z,  r);
                r = fmaf(a[c][2], x,  r);
                r = fmaf(a[c][3], y,  r);
                r = fmaf(a[c][4], b5, r);
                r = fmaf(a[c][5], b6, r);
                r = fmaf(a[c][6], b7, r);
                r = fmaf(a[c][7], b8, r);
                r = fmaf(a[c][8], b9, r);
                o[c][j] = r;
            }
        }

        float* q = ob + (size_t)(g ? v0 + 256 : v0) * 4;
        #pragma unroll
        for (int c = 0; c < 3; c++) {
            stcs4(q + (size_t)c * HW,
                  make_float4(o[c][0], o[c][1], o[c][2], o[c][3]));
        }
    }
}

extern "C" void kernel_launch(void* const* d_in, const int* in_sizes, int n_in,
                              void* d_out, int out_size) {
    const float* nrm   = (const float*)d_in[0];
    const float* light = (const float*)d_in[1];
    float* out = (float*)d_out;

    // 64 batches * 128 blocks = 8192 blocks, 256 threads,
    // 2 float4-groups per thread
    shading_kernel<<<8192, 256>>>(nrm, light, out);
}